// round 8
// baseline (speedup 1.0000x reference)
#include <cuda_runtime.h>

#define NTH 256
#define MPB 32            // matrices per block (8 lanes each)
#define RROW 16           // floats per duplicated row (8 u64 = 64B)
#define MREC 136          // floats per matrix record (8 rows + pad, 16B aligned)
#define HDR 256           // W2(64) + S2(64) + ASpair(128)
#define NSTEPS 16

typedef unsigned long long u64;

// ---- packed f32x2 primitives (sm_103a) ----
__device__ __forceinline__ u64 ffma2(u64 a, u64 b, u64 c) {
    u64 d; asm("fma.rn.f32x2 %0, %1, %2, %3;" : "=l"(d) : "l"(a), "l"(b), "l"(c)); return d;
}
__device__ __forceinline__ u64 fmul2(u64 a, u64 b) {
    u64 d; asm("mul.rn.f32x2 %0, %1, %2;" : "=l"(d) : "l"(a), "l"(b)); return d;
}
__device__ __forceinline__ u64 fadd2(u64 a, u64 b) {
    u64 d; asm("add.rn.f32x2 %0, %1, %2;" : "=l"(d) : "l"(a), "l"(b)); return d;
}
__device__ __forceinline__ u64 pk2(float x, float y) {
    u64 d; asm("mov.b64 %0, {%1, %2};" : "=l"(d) : "f"(x), "f"(y)); return d;
}
__device__ __forceinline__ float2 up2(u64 a) {
    float2 f; asm("mov.b64 {%0, %1}, %2;" : "=f"(f.x), "=f"(f.y) : "l"(a)); return f;
}
__device__ __forceinline__ u64 bc(float x) { return pk2(x, x); }

__device__ __forceinline__ float dot8p(const u64* a, const u64* b) {
    u64 s = fmul2(a[0], b[0]);
    s = ffma2(a[1], b[1], s);
    s = ffma2(a[2], b[2], s);
    s = ffma2(a[3], b[3], s);
    float2 f = up2(s);
    return f.x + f.y;
}
__device__ __forceinline__ void ldr(u64* d, const float* s) {
    ulonglong2 t0 = *(const ulonglong2*)s;
    ulonglong2 t1 = *(const ulonglong2*)(s + 4);
    d[0] = t0.x; d[1] = t0.y; d[2] = t1.x; d[3] = t1.y;
}
__device__ __forceinline__ void str(float* d, const u64* s) {
    *(ulonglong2*)d       = make_ulonglong2(s[0], s[1]);
    *(ulonglong2*)(d + 4) = make_ulonglong2(s[2], s[3]);
}

__global__ __launch_bounds__(NTH, 2)
void ode_kernel(const float* __restrict__ U0g, const float* __restrict__ epsg,
                const float* __restrict__ W0g, const float* __restrict__ W1g,
                const float* __restrict__ W2g, float* __restrict__ out, int B)
{
    extern __shared__ float sh[];
    float* W2sh = sh;         // 64: W2 row-major (init only)
    float* S2h  = sh + 64;    // 64: 0.5*(W2 - W2^T)
    float* ASP  = sh + 128;   // 128: [2*(i*8+k)] = antisym(W0)[i][k], [+1] = antisym(W1)[i][k]

    const int tid = threadIdx.x;
    if (tid < 64) {
        int ii = tid >> 3, kk = tid & 7;
        float w2  = W2g[tid];
        float w2t = W2g[kk * 8 + ii];
        W2sh[tid] = w2;
        S2h[tid]  = 0.5f * (w2 - w2t);
        ASP[2 * tid]     = 0.5f * (W0g[ii * 8 + kk] - W0g[kk * 8 + ii]);
        ASP[2 * tid + 1] = 0.5f * (W1g[ii * 8 + kk] - W1g[kk * 8 + ii]);
    }
    __syncthreads();

    const int i = tid & 7;                                  // my row
    const long bm = (long)blockIdx.x * MPB + (tid >> 3);    // my matrix
    const long bml = (bm < B) ? bm : (long)(B - 1);

    float* rUd  = sh + HDR + (size_t)(tid >> 3) * MREC;     // duplicated Us rows
    float* myUd = rUd + i * RROW;

    // ---- lane-own state ----
    u64 u[4], ub[4], ac[4];
    ldr(u, U0g + bml * 64 + i * 8);
#pragma unroll
    for (int q = 0; q < 4; q++) { ub[q] = u[q]; ac[q] = 0ull; }

    // ve[m] = pk2(v[m], e[m])  (e = v @ W2);  gpm[m] lane0 = g[m] = (W2 @ v)[m]
    u64 ve[8], gpm[8];
    {
        u64 v[4];
        ldr(v, epsg + bml * 64 + i * 8);
        u64 ep[4];
#pragma unroll
        for (int m = 0; m < 8; m++) {
            u64 w2r[4];
            ldr(w2r, W2sh + 8 * m);
            float2 vp = up2(v[m >> 1]);
            u64 a = bc((m & 1) ? vp.y : vp.x);
            if (m == 0) {
#pragma unroll
                for (int q = 0; q < 4; q++) ep[q] = fmul2(a, w2r[q]);
            } else {
#pragma unroll
                for (int q = 0; q < 4; q++) ep[q] = ffma2(a, w2r[q], ep[q]);
            }
        }
#pragma unroll
        for (int m = 0; m < 8; m++) {
            u64 w2r[4];
            ldr(w2r, W2sh + 8 * m);
            gpm[m] = pk2(dot8p(w2r, v), 0.f);   // lane0 = g[m]
        }
#pragma unroll
        for (int q = 0; q < 4; q++) {
            float2 vp = up2(v[q]);
            float2 e2 = up2(ep[q]);
            ve[2 * q]     = pk2(vp.x, e2.x);
            ve[2 * q + 1] = pk2(vp.y, e2.y);
        }
    }

    float lj = 0.f;
    const float dt = 1.0f / NSTEPS;   // T_FINAL = 1

#pragma unroll 1
    for (int st = 0; st < NSTEPS * 4; ++st) {
        const int step = st >> 2, s = st & 3;
        const float t0 = dt * (float)step;
        const float ts = t0 + ((s == 0) ? 0.f : ((s == 3) ? dt : 0.5f * dt));

        __syncwarp();            // WAR vs previous stage's reads of rUd

        // ---- unpack u, publish duplicated row ----
        float us[8];
#pragma unroll
        for (int q = 0; q < 4; q++) {
            float2 f = up2(u[q]);
            us[2 * q] = f.x; us[2 * q + 1] = f.y;
        }
        {
            u64 ud[8];
#pragma unroll
            for (int m = 0; m < 8; m++) ud[m] = bc(us[m]);
            str(myUd, ud);
            str(myUd + 8, ud + 4);
        }

        // ---- pm = u @ 0.5*(W2 - W2^T); fold into gpm lane1 ----
        {
            u64 pmp[4];
#pragma unroll
            for (int m = 0; m < 8; m++) {
                u64 s2r[4];
                ldr(s2r, S2h + 8 * m);
                u64 a = bc(us[m]);
                if (m == 0) {
#pragma unroll
                    for (int q = 0; q < 4; q++) pmp[q] = fmul2(a, s2r[q]);
                } else {
#pragma unroll
                    for (int q = 0; q < 4; q++) pmp[q] = ffma2(a, s2r[q], pmp[q]);
                }
            }
#pragma unroll
            for (int q = 0; q < 4; q++) {
                float2 pp = up2(pmp[q]);
                gpm[2 * q]     = pk2(up2(gpm[2 * q]).x,     pp.x);
                gpm[2 * q + 1] = pk2(up2(gpm[2 * q + 1]).x, pp.y);
            }
        }
        __syncwarp();            // all duplicated rows published

        // ---- rounds: dual-dot chains against duplicated U_j ----
        u64 knd[8];
        u64 xy[8];
        float zf[8];
#pragma unroll
        for (int r = 1; r < 8; ++r) {
            const int j = (i + r) & 7;
            const float* rowp = rUd + j * RROW;
            u64 Ujd[8];
            ldr(Ujd, rowp);
            ldr(Ujd + 4, rowp + 8);
            float2 as = *(const float2*)(ASP + 2 * (i * 8 + j));
            float asv = fmaf(ts, as.y, as.x);
            u64 xyacc = fmul2(ve[0], Ujd[0]);
            u64 zdacc = ffma2(gpm[0], Ujd[0], pk2(0.f, asv));
#pragma unroll
            for (int m = 1; m < 8; m++) {
                xyacc = ffma2(ve[m],  Ujd[m], xyacc);
                zdacc = ffma2(gpm[m], Ujd[m], zdacc);
            }
            xy[r] = xyacc;
            float2 zd = up2(zdacc);
            zf[r] = zd.x;                 // Z[j][i] = U_j . g_i
            u64 ab = bc(zd.y);            // A[i][j] = asv + pm.U_j
            if (r == 1) {
#pragma unroll
                for (int m = 0; m < 8; m++) knd[m] = fmul2(ab, Ujd[m]);
            } else {
#pragma unroll
                for (int m = 0; m < 8; m++) knd[m] = ffma2(ab, Ujd[m], knd[m]);
            }
        }

        // ---- repack kn to normal pair layout ----
        u64 kn[4];
#pragma unroll
        for (int q = 0; q < 4; q++)
            kn[q] = pk2(up2(knd[2 * q]).x, up2(knd[2 * q + 1]).x);

        // ---- pass 2: close antisymmetric pairs with scalar shuffles ----
        float xs[8], ys[8];
#pragma unroll
        for (int r = 1; r < 8; ++r) {
            float2 t = up2(xy[r]);
            xs[r] = t.x; ys[r] = t.y;
        }
        float lsum = 0.f;
#pragma unroll
        for (int r = 1; r < 8; ++r) {
            const int j = (i + r) & 7;
            float xji = __shfl_sync(0xffffffffu, xs[8 - r], j, 8);  // X[j][i]
            float zij = __shfl_sync(0xffffffffu, zf[8 - r], j, 8);  // Z[i][j]
            lsum = fmaf(xs[r] - xji, ys[r] + zij, lsum);
        }

        // ---- RK4 stage update ----
        const float w = dt * ((s == 1 || s == 2) ? (1.f / 3.f) : (1.f / 6.f));
        lj = fmaf(0.5f * w, lsum, lj);
        u64 wb = bc(w);
        if (s < 3) {
            float am = (s == 2) ? dt : 0.5f * dt;
            u64 ab2 = bc(am);
#pragma unroll
            for (int q = 0; q < 4; q++) {
                ac[q] = ffma2(wb, kn[q], ac[q]);
                u[q]  = ffma2(ab2, kn[q], ub[q]);
            }
        } else {
#pragma unroll
            for (int q = 0; q < 4; q++) {
                u64 t = ffma2(wb, kn[q], ac[q]);
                u[q]  = fadd2(ub[q], t);
                ub[q] = u[q];
                ac[q] = 0ull;
            }
        }
    }

    // ---- outputs ----
    if (bm < B) {
        str(out + bm * 64 + i * 8, u);
        float sred = lj;
        sred += __shfl_xor_sync(0xffffffffu, sred, 1);
        sred += __shfl_xor_sync(0xffffffffu, sred, 2);
        sred += __shfl_xor_sync(0xffffffffu, sred, 4);
        if (i == 0) out[(size_t)B * 64 + bm] = sred;
    }
}

extern "C" void kernel_launch(void* const* d_in, const int* in_sizes, int n_in,
                              void* d_out, int out_size)
{
    const float* U0  = (const float*)d_in[0];
    const float* eps = (const float*)d_in[1];
    const float* W0  = (const float*)d_in[2];
    const float* W1  = (const float*)d_in[3];
    const float* W2  = (const float*)d_in[4];

    int B = in_sizes[0] / 64;
    int smem = (HDR + MPB * MREC) * (int)sizeof(float);   // 18432 B

    cudaFuncSetAttribute(ode_kernel, cudaFuncAttributeMaxDynamicSharedMemorySize, smem);

    int blocks = (B + MPB - 1) / MPB;
    ode_kernel<<<blocks, NTH, smem>>>(U0, eps, W0, W1, W2, (float*)d_out, B);
}

// round 9
// speedup vs baseline: 2.1912x; 2.1912x over previous
#include <cuda_runtime.h>

#define NTH 256
#define MPB 32            // matrices per block (8 lanes each)
#define RROW 20           // float stride of duplicated row (j*20 mod 32 all distinct)
#define PROW 12           // float stride of packed row    (j*12 mod 32 all distinct)
#define DUPSZ 160         // 8 dup rows
#define MREC 256          // 160 dup + 96 packed
#define HDR 256           // W2(64) + S2(64) + ASpair(128)
#define NSTEPS 16

typedef unsigned long long u64;

// ---- packed f32x2 primitives (sm_103a) ----
__device__ __forceinline__ u64 ffma2(u64 a, u64 b, u64 c) {
    u64 d; asm("fma.rn.f32x2 %0, %1, %2, %3;" : "=l"(d) : "l"(a), "l"(b), "l"(c)); return d;
}
__device__ __forceinline__ u64 fmul2(u64 a, u64 b) {
    u64 d; asm("mul.rn.f32x2 %0, %1, %2;" : "=l"(d) : "l"(a), "l"(b)); return d;
}
__device__ __forceinline__ u64 fadd2(u64 a, u64 b) {
    u64 d; asm("add.rn.f32x2 %0, %1, %2;" : "=l"(d) : "l"(a), "l"(b)); return d;
}
__device__ __forceinline__ u64 pk2(float x, float y) {
    u64 d; asm("mov.b64 %0, {%1, %2};" : "=l"(d) : "f"(x), "f"(y)); return d;
}
__device__ __forceinline__ float2 up2(u64 a) {
    float2 f; asm("mov.b64 {%0, %1}, %2;" : "=f"(f.x), "=f"(f.y) : "l"(a)); return f;
}
__device__ __forceinline__ u64 bc(float x) { return pk2(x, x); }

__device__ __forceinline__ float dot8p(const u64* a, const u64* b) {
    u64 s = fmul2(a[0], b[0]);
    s = ffma2(a[1], b[1], s);
    s = ffma2(a[2], b[2], s);
    s = ffma2(a[3], b[3], s);
    float2 f = up2(s);
    return f.x + f.y;
}
__device__ __forceinline__ void ldr(u64* d, const float* s) {
    ulonglong2 t0 = *(const ulonglong2*)s;
    ulonglong2 t1 = *(const ulonglong2*)(s + 4);
    d[0] = t0.x; d[1] = t0.y; d[2] = t1.x; d[3] = t1.y;
}
__device__ __forceinline__ void str(float* d, const u64* s) {
    *(ulonglong2*)d       = make_ulonglong2(s[0], s[1]);
    *(ulonglong2*)(d + 4) = make_ulonglong2(s[2], s[3]);
}

__global__ __launch_bounds__(NTH, 2)
void ode_kernel(const float* __restrict__ U0g, const float* __restrict__ epsg,
                const float* __restrict__ W0g, const float* __restrict__ W1g,
                const float* __restrict__ W2g, float* __restrict__ out, int B)
{
    extern __shared__ float sh[];
    float* W2sh = sh;         // 64: W2 row-major (init only)
    float* S2h  = sh + 64;    // 64: 0.5*(W2 - W2^T)
    float* ASP  = sh + 128;   // 128: [2*(i*8+k)] = antisym(W0)[i][k], [+1] = antisym(W1)[i][k]

    const int tid = threadIdx.x;
    if (tid < 64) {
        int ii = tid >> 3, kk = tid & 7;
        float w2  = W2g[tid];
        float w2t = W2g[kk * 8 + ii];
        W2sh[tid] = w2;
        S2h[tid]  = 0.5f * (w2 - w2t);
        ASP[2 * tid]     = 0.5f * (W0g[ii * 8 + kk] - W0g[kk * 8 + ii]);
        ASP[2 * tid + 1] = 0.5f * (W1g[ii * 8 + kk] - W1g[kk * 8 + ii]);
    }
    __syncthreads();

    const int i = tid & 7;                                  // my row
    const long bm = (long)blockIdx.x * MPB + (tid >> 3);    // my matrix
    const long bml = (bm < B) ? bm : (long)(B - 1);

    float* rUd  = sh + HDR + (size_t)(tid >> 3) * MREC;     // duplicated rows, stride RROW
    float* rUp  = rUd + DUPSZ;                              // packed rows, stride PROW
    float* myUd = rUd + i * RROW;
    float* myUp = rUp + i * PROW;

    // ---- lane-own state ----
    u64 u[4], ub[4], ac[4];
    ldr(u, U0g + bml * 64 + i * 8);
#pragma unroll
    for (int q = 0; q < 4; q++) { ub[q] = u[q]; ac[q] = 0ull; }

    // ve[m] = pk2(v[m], e[m])  (e = v @ W2);  gpm[m] lane0 = g[m] = (W2 @ v)[m]
    u64 ve[8], gpm[8];
    {
        u64 v[4];
        ldr(v, epsg + bml * 64 + i * 8);
        u64 ep[4];
#pragma unroll
        for (int m = 0; m < 8; m++) {
            u64 w2r[4];
            ldr(w2r, W2sh + 8 * m);
            float2 vp = up2(v[m >> 1]);
            u64 a = bc((m & 1) ? vp.y : vp.x);
            if (m == 0) {
#pragma unroll
                for (int q = 0; q < 4; q++) ep[q] = fmul2(a, w2r[q]);
            } else {
#pragma unroll
                for (int q = 0; q < 4; q++) ep[q] = ffma2(a, w2r[q], ep[q]);
            }
        }
#pragma unroll
        for (int m = 0; m < 8; m++) {
            u64 w2r[4];
            ldr(w2r, W2sh + 8 * m);
            gpm[m] = pk2(dot8p(w2r, v), 0.f);   // lane0 = g[m]
        }
#pragma unroll
        for (int q = 0; q < 4; q++) {
            float2 vp = up2(v[q]);
            float2 e2 = up2(ep[q]);
            ve[2 * q]     = pk2(vp.x, e2.x);
            ve[2 * q + 1] = pk2(vp.y, e2.y);
        }
    }

    float lj = 0.f;
    const float dt = 1.0f / NSTEPS;   // T_FINAL = 1

#pragma unroll 1
    for (int st = 0; st < NSTEPS * 4; ++st) {
        const int step = st >> 2, s = st & 3;
        const float t0 = dt * (float)step;
        const float ts = t0 + ((s == 0) ? 0.f : ((s == 3) ? dt : 0.5f * dt));

        __syncwarp();            // WAR vs previous stage's reads

        // ---- unpack u, publish duplicated + packed rows ----
        float us[8];
#pragma unroll
        for (int q = 0; q < 4; q++) {
            float2 f = up2(u[q]);
            us[2 * q] = f.x; us[2 * q + 1] = f.y;
        }
        {
            u64 ud[8];
#pragma unroll
            for (int m = 0; m < 8; m++) ud[m] = bc(us[m]);
            str(myUd, ud);
            str(myUd + 8, ud + 4);
            str(myUp, u);
        }

        // ---- pm = u @ S2  (S2 = 0.5*(W2 - W2^T)); fold into gpm lane1 ----
        {
            u64 pmp[4];
#pragma unroll
            for (int m = 0; m < 8; m++) {
                u64 s2r[4];
                ldr(s2r, S2h + 8 * m);
                u64 a = bc(us[m]);
                if (m == 0) {
#pragma unroll
                    for (int q = 0; q < 4; q++) pmp[q] = fmul2(a, s2r[q]);
                } else {
#pragma unroll
                    for (int q = 0; q < 4; q++) pmp[q] = ffma2(a, s2r[q], pmp[q]);
                }
            }
#pragma unroll
            for (int q = 0; q < 4; q++) {
                float2 pp = up2(pmp[q]);
                gpm[2 * q]     = pk2(up2(gpm[2 * q]).x,     pp.x);
                gpm[2 * q + 1] = pk2(up2(gpm[2 * q + 1]).x, pp.y);
            }
        }
        __syncwarp();            // all rows published

        // ---- rounds: dual-dot chains on dup rows, kn on packed rows ----
        u64 kn[4];
        u64 xy[8];
        float zf[8];
#pragma unroll
        for (int r = 1; r < 8; ++r) {
            const int j = (i + r) & 7;
            const float* rowd = rUd + j * RROW;
            u64 Ujd[8], Uj[4];
            ldr(Ujd, rowd);
            ldr(Ujd + 4, rowd + 8);
            ldr(Uj, rUp + j * PROW);
            float2 as = *(const float2*)(ASP + 2 * (i * 8 + j));
            float asv = fmaf(ts, as.y, as.x);
            u64 xyacc = fmul2(ve[0], Ujd[0]);
            u64 zdacc = ffma2(gpm[0], Ujd[0], pk2(0.f, asv));
#pragma unroll
            for (int m = 1; m < 8; m++) {
                xyacc = ffma2(ve[m],  Ujd[m], xyacc);
                zdacc = ffma2(gpm[m], Ujd[m], zdacc);
            }
            xy[r] = xyacc;
            float2 zd = up2(zdacc);
            zf[r] = zd.x;                 // Z[j][i] = U_j . g_i
            u64 ab = bc(zd.y);            // A[i][j] = asv + pm . U_j
            if (r == 1) {
#pragma unroll
                for (int q = 0; q < 4; q++) kn[q] = fmul2(ab, Uj[q]);
            } else {
#pragma unroll
                for (int q = 0; q < 4; q++) kn[q] = ffma2(ab, Uj[q], kn[q]);
            }
        }

        // ---- pass 2: close antisymmetric pairs with scalar shuffles ----
        float xs[8], ys[8];
#pragma unroll
        for (int r = 1; r < 8; ++r) {
            float2 t = up2(xy[r]);
            xs[r] = t.x; ys[r] = t.y;
        }
        float lsum = 0.f;
#pragma unroll
        for (int r = 1; r < 8; ++r) {
            const int j = (i + r) & 7;
            float xji = __shfl_sync(0xffffffffu, xs[8 - r], j, 8);  // X[j][i]
            float zij = __shfl_sync(0xffffffffu, zf[8 - r], j, 8);  // Z[i][j]
            lsum = fmaf(xs[r] - xji, ys[r] + zij, lsum);
        }

        // ---- RK4 stage update ----
        const float w = dt * ((s == 1 || s == 2) ? (1.f / 3.f) : (1.f / 6.f));
        lj = fmaf(0.5f * w, lsum, lj);
        u64 wb = bc(w);
        if (s < 3) {
            float am = (s == 2) ? dt : 0.5f * dt;
            u64 ab2 = bc(am);
#pragma unroll
            for (int q = 0; q < 4; q++) {
                ac[q] = ffma2(wb, kn[q], ac[q]);
                u[q]  = ffma2(ab2, kn[q], ub[q]);
            }
        } else {
#pragma unroll
            for (int q = 0; q < 4; q++) {
                u64 t = ffma2(wb, kn[q], ac[q]);
                u[q]  = fadd2(ub[q], t);
                ub[q] = u[q];
                ac[q] = 0ull;
            }
        }
    }

    // ---- outputs ----
    if (bm < B) {
        str(out + bm * 64 + i * 8, u);
        float sred = lj;
        sred += __shfl_xor_sync(0xffffffffu, sred, 1);
        sred += __shfl_xor_sync(0xffffffffu, sred, 2);
        sred += __shfl_xor_sync(0xffffffffu, sred, 4);
        if (i == 0) out[(size_t)B * 64 + bm] = sred;
    }
}

extern "C" void kernel_launch(void* const* d_in, const int* in_sizes, int n_in,
                              void* d_out, int out_size)
{
    const float* U0  = (const float*)d_in[0];
    const float* eps = (const float*)d_in[1];
    const float* W0  = (const float*)d_in[2];
    const float* W1  = (const float*)d_in[3];
    const float* W2  = (const float*)d_in[4];

    int B = in_sizes[0] / 64;
    int smem = (HDR + MPB * MREC) * (int)sizeof(float);   // 33792 B

    cudaFuncSetAttribute(ode_kernel, cudaFuncAttributeMaxDynamicSharedMemorySize, smem);

    int blocks = (B + MPB - 1) / MPB;
    ode_kernel<<<blocks, NTH, smem>>>(U0, eps, W0, W1, W2, (float*)d_out, B);
}

// round 10
// speedup vs baseline: 3.9230x; 1.7903x over previous
#include <cuda_runtime.h>

#define NTH 256
#define MPB 32            // matrices per block (8 lanes each)
#define PROW 12           // float stride of packed row (j*12 mod 32 all distinct)
#define MREC 104          // floats per matrix record (8 rows * 12 + pad, 16B-aligned)
#define HDR 256           // W2(64) + S2(64) + ASpair(128)
#define NSTEPS 16

typedef unsigned long long u64;

// ---- packed f32x2 primitives (sm_103a) ----
__device__ __forceinline__ u64 ffma2(u64 a, u64 b, u64 c) {
    u64 d; asm("fma.rn.f32x2 %0, %1, %2, %3;" : "=l"(d) : "l"(a), "l"(b), "l"(c)); return d;
}
__device__ __forceinline__ u64 fmul2(u64 a, u64 b) {
    u64 d; asm("mul.rn.f32x2 %0, %1, %2;" : "=l"(d) : "l"(a), "l"(b)); return d;
}
__device__ __forceinline__ u64 fadd2(u64 a, u64 b) {
    u64 d; asm("add.rn.f32x2 %0, %1, %2;" : "=l"(d) : "l"(a), "l"(b)); return d;
}
__device__ __forceinline__ u64 pk2(float x, float y) {
    u64 d; asm("mov.b64 %0, {%1, %2};" : "=l"(d) : "f"(x), "f"(y)); return d;
}
__device__ __forceinline__ float2 up2(u64 a) {
    float2 f; asm("mov.b64 {%0, %1}, %2;" : "=f"(f.x), "=f"(f.y) : "l"(a)); return f;
}
__device__ __forceinline__ u64 bc(float x) { return pk2(x, x); }

__device__ __forceinline__ float dot8p(const u64* a, const u64* b) {
    u64 s = fmul2(a[0], b[0]);
    s = ffma2(a[1], b[1], s);
    s = ffma2(a[2], b[2], s);
    s = ffma2(a[3], b[3], s);
    float2 f = up2(s);
    return f.x + f.y;
}
__device__ __forceinline__ void ldr(u64* d, const float* s) {
    ulonglong2 t0 = *(const ulonglong2*)s;
    ulonglong2 t1 = *(const ulonglong2*)(s + 4);
    d[0] = t0.x; d[1] = t0.y; d[2] = t1.x; d[3] = t1.y;
}
__device__ __forceinline__ void str(float* d, const u64* s) {
    *(ulonglong2*)d       = make_ulonglong2(s[0], s[1]);
    *(ulonglong2*)(d + 4) = make_ulonglong2(s[2], s[3]);
}

__global__ __launch_bounds__(NTH, 2)
void ode_kernel(const float* __restrict__ U0g, const float* __restrict__ epsg,
                const float* __restrict__ W0g, const float* __restrict__ W1g,
                const float* __restrict__ W2g, float* __restrict__ out, int B)
{
    extern __shared__ float sh[];
    float* W2sh = sh;         // 64: W2 row-major (init only)
    float* S2h  = sh + 64;    // 64: 0.5*(W2 - W2^T)
    float* ASP  = sh + 128;   // 128: [2*(i*8+k)] = antisym(W0)[i][k], [+1] = antisym(W1)[i][k]

    const int tid = threadIdx.x;
    if (tid < 64) {
        int ii = tid >> 3, kk = tid & 7;
        float w2  = W2g[tid];
        float w2t = W2g[kk * 8 + ii];
        W2sh[tid] = w2;
        S2h[tid]  = 0.5f * (w2 - w2t);
        ASP[2 * tid]     = 0.5f * (W0g[ii * 8 + kk] - W0g[kk * 8 + ii]);
        ASP[2 * tid + 1] = 0.5f * (W1g[ii * 8 + kk] - W1g[kk * 8 + ii]);
    }
    __syncthreads();

    const int i = tid & 7;                                  // my row
    const long bm = (long)blockIdx.x * MPB + (tid >> 3);    // my matrix
    const long bml = (bm < B) ? bm : (long)(B - 1);

    float* rUp  = sh + HDR + (size_t)(tid >> 3) * MREC;     // packed Us rows, stride PROW
    float* myUp = rUp + i * PROW;

    // ---- lane-own state ----
    u64 u[4], ub[4], ac[4], v[4], e[4], g[4];
    ldr(u, U0g + bml * 64 + i * 8);
    ldr(v, epsg + bml * 64 + i * 8);
#pragma unroll
    for (int q = 0; q < 4; q++) { ub[q] = u[q]; ac[q] = 0ull; }

    // e = v @ W2 (row);  g[m] = (W2 @ v)[m]  -> packed
    {
#pragma unroll
        for (int m = 0; m < 8; m++) {
            u64 w2r[4];
            ldr(w2r, W2sh + 8 * m);
            float2 vp = up2(v[m >> 1]);
            u64 a = bc((m & 1) ? vp.y : vp.x);
            if (m == 0) {
#pragma unroll
                for (int q = 0; q < 4; q++) e[q] = fmul2(a, w2r[q]);
            } else {
#pragma unroll
                for (int q = 0; q < 4; q++) e[q] = ffma2(a, w2r[q], e[q]);
            }
        }
        float gs[8];
#pragma unroll
        for (int m = 0; m < 8; m++) {
            u64 w2r[4];
            ldr(w2r, W2sh + 8 * m);
            gs[m] = dot8p(w2r, v);
        }
#pragma unroll
        for (int q = 0; q < 4; q++) g[q] = pk2(gs[2 * q], gs[2 * q + 1]);
    }

    // ---- hoist AS pairs for my row into registers (constant over trajectory) ----
    float as0[8], as1[8];
#pragma unroll
    for (int r = 1; r < 8; ++r) {
        const int j = (i + r) & 7;
        float2 as = *(const float2*)(ASP + 2 * (i * 8 + j));
        as0[r] = as.x; as1[r] = as.y;
    }

    float lj = 0.f;
    const float dt = 1.0f / NSTEPS;   // T_FINAL = 1

#pragma unroll 1
    for (int st = 0; st < NSTEPS * 4; ++st) {
        const int step = st >> 2, s = st & 3;
        const float t0 = dt * (float)step;
        const float ts = t0 + ((s == 0) ? 0.f : ((s == 3) ? dt : 0.5f * dt));

        __syncwarp();            // WAR vs previous stage's reads of rUp
        str(myUp, u);            // publish my packed row

        // ---- pm = u @ S2  (S2 = 0.5*(W2 - W2^T) prescaled; broadcast loads) ----
        u64 pm[4];
#pragma unroll
        for (int m = 0; m < 8; m++) {
            u64 s2r[4];
            ldr(s2r, S2h + 8 * m);
            float2 upv = up2(u[m >> 1]);
            u64 a = bc((m & 1) ? upv.y : upv.x);
            if (m == 0) {
#pragma unroll
                for (int q = 0; q < 4; q++) pm[q] = fmul2(a, s2r[q]);
            } else {
#pragma unroll
                for (int q = 0; q < 4; q++) pm[q] = ffma2(a, s2r[q], pm[q]);
            }
        }
        __syncwarp();            // all rows published

        // ---- rounds: 4 packed dots + kn accumulate against U_j ----
        u64 kn[4];
        float xs[8], ys[8], zf[8];
#pragma unroll
        for (int r = 1; r < 8; ++r) {
            const int j = (i + r) & 7;
            u64 Uj[4];
            ldr(Uj, rUp + j * PROW);
            xs[r] = dot8p(v, Uj);                       // X[i][j]
            ys[r] = dot8p(e, Uj);                       // Y[i][j]
            zf[r] = dot8p(g, Uj);                       // Z[j][i]
            float a = fmaf(ts, as1[r], as0[r]) + dot8p(pm, Uj);   // A[i][j]
            u64 ab = bc(a);
            if (r == 1) {
#pragma unroll
                for (int q = 0; q < 4; q++) kn[q] = fmul2(ab, Uj[q]);
            } else {
#pragma unroll
                for (int q = 0; q < 4; q++) kn[q] = ffma2(ab, Uj[q], kn[q]);
            }
        }

        // ---- pass 2: close antisymmetric pairs with scalar shuffles ----
        float lsum = 0.f;
#pragma unroll
        for (int r = 1; r < 8; ++r) {
            const int j = (i + r) & 7;
            float xji = __shfl_sync(0xffffffffu, xs[8 - r], j, 8);  // X[j][i]
            float zij = __shfl_sync(0xffffffffu, zf[8 - r], j, 8);  // Z[i][j]
            lsum = fmaf(xs[r] - xji, ys[r] + zij, lsum);
        }

        // ---- RK4 stage update ----
        const float w = dt * ((s == 1 || s == 2) ? (1.f / 3.f) : (1.f / 6.f));
        lj = fmaf(0.5f * w, lsum, lj);
        u64 wb = bc(w);
        if (s < 3) {
            float am = (s == 2) ? dt : 0.5f * dt;
            u64 ab2 = bc(am);
#pragma unroll
            for (int q = 0; q < 4; q++) {
                ac[q] = ffma2(wb, kn[q], ac[q]);
                u[q]  = ffma2(ab2, kn[q], ub[q]);
            }
        } else {
#pragma unroll
            for (int q = 0; q < 4; q++) {
                u64 t = ffma2(wb, kn[q], ac[q]);
                u[q]  = fadd2(ub[q], t);
                ub[q] = u[q];
                ac[q] = 0ull;
            }
        }
    }

    // ---- outputs ----
    if (bm < B) {
        str(out + bm * 64 + i * 8, u);
        float sred = lj;
        sred += __shfl_xor_sync(0xffffffffu, sred, 1);
        sred += __shfl_xor_sync(0xffffffffu, sred, 2);
        sred += __shfl_xor_sync(0xffffffffu, sred, 4);
        if (i == 0) out[(size_t)B * 64 + bm] = sred;
    }
}

extern "C" void kernel_launch(void* const* d_in, const int* in_sizes, int n_in,
                              void* d_out, int out_size)
{
    const float* U0  = (const float*)d_in[0];
    const float* eps = (const float*)d_in[1];
    const float* W0  = (const float*)d_in[2];
    const float* W1  = (const float*)d_in[3];
    const float* W2  = (const float*)d_in[4];

    int B = in_sizes[0] / 64;
    int smem = (HDR + MPB * MREC) * (int)sizeof(float);   // 14336 B

    cudaFuncSetAttribute(ode_kernel, cudaFuncAttributeMaxDynamicSharedMemorySize, smem);

    int blocks = (B + MPB - 1) / MPB;
    ode_kernel<<<blocks, NTH, smem>>>(U0, eps, W0, W1, W2, (float*)d_out, B);
}

// round 14
// speedup vs baseline: 3.9680x; 1.0115x over previous
#include <cuda_runtime.h>

#define NTH 256
#define MPB 32            // matrices per block (8 lanes each)
#define PROW 12           // float stride of packed row (j*12 mod 32 all distinct, 4-aligned)
#define BUFSZ 104         // one row buffer (8*12 + pad, 16B-aligned)
#define MREC 208          // two buffers (double-buffered stages)
#define HDR 256           // W2(64) + S2(64) + ASpair(128)
#define NSTEPS 16

typedef unsigned long long u64;

// ---- packed f32x2 primitives (sm_103a) ----
__device__ __forceinline__ u64 ffma2(u64 a, u64 b, u64 c) {
    u64 d; asm("fma.rn.f32x2 %0, %1, %2, %3;" : "=l"(d) : "l"(a), "l"(b), "l"(c)); return d;
}
__device__ __forceinline__ u64 fmul2(u64 a, u64 b) {
    u64 d; asm("mul.rn.f32x2 %0, %1, %2;" : "=l"(d) : "l"(a), "l"(b)); return d;
}
__device__ __forceinline__ u64 fadd2(u64 a, u64 b) {
    u64 d; asm("add.rn.f32x2 %0, %1, %2;" : "=l"(d) : "l"(a), "l"(b)); return d;
}
__device__ __forceinline__ u64 pk2(float x, float y) {
    u64 d; asm("mov.b64 %0, {%1, %2};" : "=l"(d) : "f"(x), "f"(y)); return d;
}
__device__ __forceinline__ float2 up2(u64 a) {
    float2 f; asm("mov.b64 {%0, %1}, %2;" : "=f"(f.x), "=f"(f.y) : "l"(a)); return f;
}
__device__ __forceinline__ u64 bc(float x) { return pk2(x, x); }

__device__ __forceinline__ float dot8p(const u64* a, const u64* b) {
    u64 s = fmul2(a[0], b[0]);
    s = ffma2(a[1], b[1], s);
    s = ffma2(a[2], b[2], s);
    s = ffma2(a[3], b[3], s);
    float2 f = up2(s);
    return f.x + f.y;
}
__device__ __forceinline__ void ldr(u64* d, const float* s) {
    ulonglong2 t0 = *(const ulonglong2*)s;
    ulonglong2 t1 = *(const ulonglong2*)(s + 4);
    d[0] = t0.x; d[1] = t0.y; d[2] = t1.x; d[3] = t1.y;
}
__device__ __forceinline__ void str(float* d, const u64* s) {
    *(ulonglong2*)d       = make_ulonglong2(s[0], s[1]);
    *(ulonglong2*)(d + 4) = make_ulonglong2(s[2], s[3]);
}

__global__ __launch_bounds__(NTH, 2)
void ode_kernel(const float* __restrict__ U0g, const float* __restrict__ epsg,
                const float* __restrict__ W0g, const float* __restrict__ W1g,
                const float* __restrict__ W2g, float* __restrict__ out, int B)
{
    extern __shared__ float sh[];
    float* W2sh = sh;         // 64: W2 row-major (init only)
    float* S2h  = sh + 64;    // 64: 0.5*(W2 - W2^T)
    float* ASP  = sh + 128;   // 128: [2*(i*8+k)] = antisym(W0)[i][k], [+1] = antisym(W1)[i][k]

    const int tid = threadIdx.x;
    if (tid < 64) {
        int ii = tid >> 3, kk = tid & 7;
        float w2  = W2g[tid];
        float w2t = W2g[kk * 8 + ii];
        W2sh[tid] = w2;
        S2h[tid]  = 0.5f * (w2 - w2t);
        ASP[2 * tid]     = 0.5f * (W0g[ii * 8 + kk] - W0g[kk * 8 + ii]);
        ASP[2 * tid + 1] = 0.5f * (W1g[ii * 8 + kk] - W1g[kk * 8 + ii]);
    }
    __syncthreads();

    const int i = tid & 7;                                  // my row
    const long bm = (long)blockIdx.x * MPB + (tid >> 3);    // my matrix
    const long bml = (bm < B) ? bm : (long)(B - 1);

    float* rUp = sh + HDR + (size_t)(tid >> 3) * MREC;      // 2 packed row buffers

    // ---- lane-own state ----
    u64 u[4], ub[4], ac[4], ve[8], gpk[4];
    ldr(u, U0g + bml * 64 + i * 8);
#pragma unroll
    for (int q = 0; q < 4; q++) { ub[q] = u[q]; ac[q] = 0ull; }

    // v, e = v@W2 (row), g = W2@v (col-form); pack ve[m] = (v_m, e_m), gpk = packed g
    {
        u64 v[4], e[4];
        ldr(v, epsg + bml * 64 + i * 8);
#pragma unroll
        for (int m = 0; m < 8; m++) {
            u64 w2r[4];
            ldr(w2r, W2sh + 8 * m);
            float2 vp = up2(v[m >> 1]);
            u64 a = bc((m & 1) ? vp.y : vp.x);
            if (m == 0) {
#pragma unroll
                for (int q = 0; q < 4; q++) e[q] = fmul2(a, w2r[q]);
            } else {
#pragma unroll
                for (int q = 0; q < 4; q++) e[q] = ffma2(a, w2r[q], e[q]);
            }
        }
        float gs[8];
#pragma unroll
        for (int m = 0; m < 8; m++) {
            u64 w2r[4];
            ldr(w2r, W2sh + 8 * m);
            gs[m] = dot8p(w2r, v);
        }
#pragma unroll
        for (int q = 0; q < 4; q++) {
            float2 vp = up2(v[q]);
            float2 e2 = up2(e[q]);
            ve[2 * q]     = pk2(vp.x, e2.x);
            ve[2 * q + 1] = pk2(vp.y, e2.y);
            gpk[q] = pk2(gs[2 * q], gs[2 * q + 1]);
        }
    }

    float lj = 0.f;
    const float dt = 1.0f / NSTEPS;   // T_FINAL = 1
    const float* myASP = ASP + 16 * i;

#pragma unroll 1
    for (int st = 0; st < NSTEPS * 4; ++st) {
        const int step = st >> 2, s = st & 3;
        const float t0 = dt * (float)step;
        const float ts = t0 + ((s == 0) ? 0.f : ((s == 3) ? dt : 0.5f * dt));

        float* rbuf = rUp + (st & 1) * BUFSZ;   // double buffer: one syncwarp/stage
        str(rbuf + i * PROW, u);                // publish my packed row

        // ---- pm = u @ S2  (S2 = 0.5*(W2 - W2^T) prescaled; broadcast loads) ----
        u64 pm[4];
#pragma unroll
        for (int m = 0; m < 8; m++) {
            u64 s2r[4];
            ldr(s2r, S2h + 8 * m);
            float2 upv = up2(u[m >> 1]);
            u64 a = bc((m & 1) ? upv.y : upv.x);
            if (m == 0) {
#pragma unroll
                for (int q = 0; q < 4; q++) pm[q] = fmul2(a, s2r[q]);
            } else {
#pragma unroll
                for (int q = 0; q < 4; q++) pm[q] = ffma2(a, s2r[q], pm[q]);
            }
        }
        // gpm[m] = (g_m, pm_m)  (unpacks are register halves; pk2 on ALU pipe)
        u64 gpm[8];
#pragma unroll
        for (int q = 0; q < 4; q++) {
            float2 gg = up2(gpk[q]);
            float2 pp = up2(pm[q]);
            gpm[2 * q]     = pk2(gg.x, pp.x);
            gpm[2 * q + 1] = pk2(gg.y, pp.y);
        }
        __syncwarp();            // all rows of this buffer published

        // ---- rounds: 2 dual chains + kn against packed U_j ----
        u64 kn[4];
        u64 xy[8];
        float zf[8];
#pragma unroll
        for (int r = 1; r < 8; ++r) {
            const int j = (i + r) & 7;
            u64 Uj[4];
            ldr(Uj, rbuf + j * PROW);
            float2 as2 = *(const float2*)(myASP + 2 * j);
            // build duplicated operand in registers (ALU movs, fma pipe untouched)
            u64 Ujd[8];
#pragma unroll
            for (int q = 0; q < 4; q++) {
                float2 f = up2(Uj[q]);
                Ujd[2 * q]     = bc(f.x);
                Ujd[2 * q + 1] = bc(f.y);
            }
            u64 xyacc = fmul2(ve[0],  Ujd[0]);
            u64 zacc  = fmul2(gpm[0], Ujd[0]);
#pragma unroll
            for (int m = 1; m < 8; m++) {
                xyacc = ffma2(ve[m],  Ujd[m], xyacc);
                zacc  = ffma2(gpm[m], Ujd[m], zacc);
            }
            xy[r] = xyacc;                   // lane0 = X[i][j], lane1 = Y[i][j]
            float2 zA = up2(zacc);
            zf[r] = zA.x;                    // Z[j][i] = U_j . g_i
            float a = fmaf(ts, as2.y, as2.x) + zA.y;   // A[i][j]
            u64 ab = bc(a);
            if (r == 1) {
#pragma unroll
                for (int q = 0; q < 4; q++) kn[q] = fmul2(ab, Uj[q]);
            } else {
#pragma unroll
                for (int q = 0; q < 4; q++) kn[q] = ffma2(ab, Uj[q], kn[q]);
            }
        }

        // ---- closure: antisymmetric pairs via scalar shuffles ----
        float lsum = 0.f;
#pragma unroll
        for (int r = 1; r < 8; ++r) {
            const int j = (i + r) & 7;
            float2 mine = up2(xy[r]);
            float xji = __shfl_sync(0xffffffffu, up2(xy[8 - r]).x, j, 8);  // X[j][i]
            float zij = __shfl_sync(0xffffffffu, zf[8 - r], j, 8);         // Z[i][j]
            lsum = fmaf(mine.x - xji, mine.y + zij, lsum);
        }

        // ---- RK4 stage update ----
        const float w = dt * ((s == 1 || s == 2) ? (1.f / 3.f) : (1.f / 6.f));
        lj = fmaf(0.5f * w, lsum, lj);
        u64 wb = bc(w);
        if (s < 3) {
            float am = (s == 2) ? dt : 0.5f * dt;
            u64 ab2 = bc(am);
#pragma unroll
            for (int q = 0; q < 4; q++) {
                ac[q] = ffma2(wb, kn[q], ac[q]);
                u[q]  = ffma2(ab2, kn[q], ub[q]);
            }
        } else {
#pragma unroll
            for (int q = 0; q < 4; q++) {
                u64 t = ffma2(wb, kn[q], ac[q]);
                u[q]  = fadd2(ub[q], t);
                ub[q] = u[q];
                ac[q] = 0ull;
            }
        }
    }

    // ---- outputs ----
    if (bm < B) {
        str(out + bm * 64 + i * 8, u);
        float sred = lj;
        sred += __shfl_xor_sync(0xffffffffu, sred, 1);
        sred += __shfl_xor_sync(0xffffffffu, sred, 2);
        sred += __shfl_xor_sync(0xffffffffu, sred, 4);
        if (i == 0) out[(size_t)B * 64 + bm] = sred;
    }
}

extern "C" void kernel_launch(void* const* d_in, const int* in_sizes, int n_in,
                              void* d_out, int out_size)
{
    const float* U0  = (const float*)d_in[0];
    const float* eps = (const float*)d_in[1];
    const float* W0  = (const float*)d_in[2];
    const float* W1  = (const float*)d_in[3];
    const float* W2  = (const float*)d_in[4];

    int B = in_sizes[0] / 64;
    int smem = (HDR + MPB * MREC) * (int)sizeof(float);   // 27648 B

    cudaFuncSetAttribute(ode_kernel, cudaFuncAttributeMaxDynamicSharedMemorySize, smem);

    int blocks = (B + MPB - 1) / MPB;
    ode_kernel<<<blocks, NTH, smem>>>(U0, eps, W0, W1, W2, (float*)d_out, B);
}

// round 16
// speedup vs baseline: 4.7714x; 1.2025x over previous
#include <cuda_runtime.h>

#define NTH 256
#define MPB 32            // matrices per block (8 lanes each)
#define PROW 12           // float stride of packed row (j*12 mod 32 all distinct, 4-aligned)
#define BUFSZ 104         // one row buffer (8*12 + pad, 16B-aligned)
#define MREC 208          // two buffers (double-buffered stages)
#define HDR 192           // S2(64) + ASpair(128)
#define NSTEPS 16

typedef unsigned long long u64;

// ---- packed f32x2 primitives (sm_103a) ----
__device__ __forceinline__ u64 ffma2(u64 a, u64 b, u64 c) {
    u64 d; asm("fma.rn.f32x2 %0, %1, %2, %3;" : "=l"(d) : "l"(a), "l"(b), "l"(c)); return d;
}
__device__ __forceinline__ u64 fmul2(u64 a, u64 b) {
    u64 d; asm("mul.rn.f32x2 %0, %1, %2;" : "=l"(d) : "l"(a), "l"(b)); return d;
}
__device__ __forceinline__ u64 fadd2(u64 a, u64 b) {
    u64 d; asm("add.rn.f32x2 %0, %1, %2;" : "=l"(d) : "l"(a), "l"(b)); return d;
}
__device__ __forceinline__ u64 pk2(float x, float y) {
    u64 d; asm("mov.b64 %0, {%1, %2};" : "=l"(d) : "f"(x), "f"(y)); return d;
}
__device__ __forceinline__ float2 up2(u64 a) {
    float2 f; asm("mov.b64 {%0, %1}, %2;" : "=f"(f.x), "=f"(f.y) : "l"(a)); return f;
}
__device__ __forceinline__ u64 bc(float x) { return pk2(x, x); }

__device__ __forceinline__ void ldr(u64* d, const float* s) {
    ulonglong2 t0 = *(const ulonglong2*)s;
    ulonglong2 t1 = *(const ulonglong2*)(s + 4);
    d[0] = t0.x; d[1] = t0.y; d[2] = t1.x; d[3] = t1.y;
}
__device__ __forceinline__ void str(float* d, const u64* s) {
    *(ulonglong2*)d       = make_ulonglong2(s[0], s[1]);
    *(ulonglong2*)(d + 4) = make_ulonglong2(s[2], s[3]);
}

__global__ __launch_bounds__(NTH, 2)
void ode_kernel(const float* __restrict__ U0g, const float* __restrict__ epsg,
                const float* __restrict__ W0g, const float* __restrict__ W1g,
                const float* __restrict__ W2g, float* __restrict__ out, int B)
{
    extern __shared__ float sh[];
    float* S2h = sh;          // 64: 0.5*(W2 - W2^T)
    float* ASP = sh + 64;     // 128: [2*(i*8+k)] = antisym(W0)[i][k], [+1] = antisym(W1)[i][k]

    const int tid = threadIdx.x;
    if (tid < 64) {
        int ii = tid >> 3, kk = tid & 7;
        S2h[tid]         = 0.5f * (W2g[ii * 8 + kk] - W2g[kk * 8 + ii]);
        ASP[2 * tid]     = 0.5f * (W0g[ii * 8 + kk] - W0g[kk * 8 + ii]);
        ASP[2 * tid + 1] = 0.5f * (W1g[ii * 8 + kk] - W1g[kk * 8 + ii]);
    }
    __syncthreads();

    const int i = tid & 7;                                  // my row
    const long bm = (long)blockIdx.x * MPB + (tid >> 3);    // my matrix
    const long bml = (bm < B) ? bm : (long)(B - 1);

    float* rUp = sh + HDR + (size_t)(tid >> 3) * MREC;      // 2 packed row buffers

    // ---- lane-own state ----
    u64 u[4], ub[4], ac[4], vh[8];
    ldr(u, U0g + bml * 64 + i * 8);
#pragma unroll
    for (int q = 0; q < 4; q++) { ub[q] = u[q]; ac[q] = 0ull; }

    // h = v @ S2 (constant over trajectory); vh[m] = pk2(v_m, h_m)
    {
        u64 v[4], h[4];
        ldr(v, epsg + bml * 64 + i * 8);
#pragma unroll
        for (int m = 0; m < 8; m++) {
            u64 s2r[4];
            ldr(s2r, S2h + 8 * m);
            float2 vp = up2(v[m >> 1]);
            u64 a = bc((m & 1) ? vp.y : vp.x);
            if (m == 0) {
#pragma unroll
                for (int q = 0; q < 4; q++) h[q] = fmul2(a, s2r[q]);
            } else {
#pragma unroll
                for (int q = 0; q < 4; q++) h[q] = ffma2(a, s2r[q], h[q]);
            }
        }
#pragma unroll
        for (int q = 0; q < 4; q++) {
            float2 vp = up2(v[q]);
            float2 hp = up2(h[q]);
            vh[2 * q]     = pk2(vp.x, hp.x);
            vh[2 * q + 1] = pk2(vp.y, hp.y);
        }
    }

    // ---- hoist AS pairs for my row into registers (constant over trajectory) ----
    float as0[8], as1[8];
#pragma unroll
    for (int r = 1; r < 8; ++r) {
        const int j = (i + r) & 7;
        float2 as = *(const float2*)(ASP + 2 * (i * 8 + j));
        as0[r] = as.x; as1[r] = as.y;
    }

    float lj = 0.f;
    const float dt = 1.0f / NSTEPS;   // T_FINAL = 1

#pragma unroll 1
    for (int st = 0; st < NSTEPS * 4; ++st) {
        const int step = st >> 2, s = st & 3;
        const float t0 = dt * (float)step;
        const float ts = t0 + ((s == 0) ? 0.f : ((s == 3) ? dt : 0.5f * dt));

        float* rbuf = rUp + (st & 1) * BUFSZ;   // double buffer: one syncwarp/stage
        str(rbuf + i * PROW, u);                // publish my packed row

        // ---- pm = u @ S2 (broadcast loads of prescaled antisym table) ----
        u64 pm[4];
#pragma unroll
        for (int m = 0; m < 8; m++) {
            u64 s2r[4];
            ldr(s2r, S2h + 8 * m);
            float2 upv = up2(u[m >> 1]);
            u64 a = bc((m & 1) ? upv.y : upv.x);
            if (m == 0) {
#pragma unroll
                for (int q = 0; q < 4; q++) pm[q] = fmul2(a, s2r[q]);
            } else {
#pragma unroll
                for (int q = 0; q < 4; q++) pm[q] = ffma2(a, s2r[q], pm[q]);
            }
        }
        __syncwarp();            // all rows of this buffer published

        // ---- rounds: dual (X,H) chain + seeded A-dot + kn ----
        u64 kn[4];
        u64 xh[8];
#pragma unroll
        for (int r = 1; r < 8; ++r) {
            const int j = (i + r) & 7;
            u64 Uj[4];
            ldr(Uj, rbuf + j * PROW);
            float asv = fmaf(ts, as1[r], as0[r]);
            // duplicated operand in registers (ALU movs)
            u64 Ujd[8];
#pragma unroll
            for (int q = 0; q < 4; q++) {
                float2 f = up2(Uj[q]);
                Ujd[2 * q]     = bc(f.x);
                Ujd[2 * q + 1] = bc(f.y);
            }
            // chain 1: (X[i][j], H[i][j]) = (v.Uj, h.Uj)
            u64 xhacc = fmul2(vh[0], Ujd[0]);
#pragma unroll
            for (int m = 1; m < 8; m++) xhacc = ffma2(vh[m], Ujd[m], xhacc);
            xh[r] = xhacc;
            // chain 2: A[i][j] = asv + pm . Uj  (seeded packed dot)
            u64 aacc = ffma2(pm[0], Uj[0], pk2(asv, 0.f));
            aacc = ffma2(pm[1], Uj[1], aacc);
            aacc = ffma2(pm[2], Uj[2], aacc);
            aacc = ffma2(pm[3], Uj[3], aacc);
            float2 ap = up2(aacc);
            u64 ab = bc(ap.x + ap.y);
            if (r == 1) {
#pragma unroll
                for (int q = 0; q < 4; q++) kn[q] = fmul2(ab, Uj[q]);
            } else {
#pragma unroll
                for (int q = 0; q < 4; q++) kn[q] = ffma2(ab, Uj[q], kn[q]);
            }
        }

        // ---- closure: lsum = sum_j (X[i][j] - X[j][i]) * H[i][j] ----
        float lsum = 0.f;
#pragma unroll
        for (int r = 1; r < 8; ++r) {
            const int j = (i + r) & 7;
            float2 mine = up2(xh[r]);
            float xji = __shfl_sync(0xffffffffu, up2(xh[8 - r]).x, j, 8);  // X[j][i]
            lsum = fmaf(mine.x - xji, mine.y, lsum);
        }

        // ---- RK4 stage update ----
        const float w = dt * ((s == 1 || s == 2) ? (1.f / 3.f) : (1.f / 6.f));
        lj = fmaf(w, lsum, lj);          // factor 2 from identity cancels the 0.5
        u64 wb = bc(w);
        if (s < 3) {
            float am = (s == 2) ? dt : 0.5f * dt;
            u64 ab2 = bc(am);
#pragma unroll
            for (int q = 0; q < 4; q++) {
                ac[q] = ffma2(wb, kn[q], ac[q]);
                u[q]  = ffma2(ab2, kn[q], ub[q]);
            }
        } else {
#pragma unroll
            for (int q = 0; q < 4; q++) {
                u64 t = ffma2(wb, kn[q], ac[q]);
                u[q]  = fadd2(ub[q], t);
                ub[q] = u[q];
                ac[q] = 0ull;
            }
        }
    }

    // ---- outputs ----
    if (bm < B) {
        str(out + bm * 64 + i * 8, u);
        float sred = lj;
        sred += __shfl_xor_sync(0xffffffffu, sred, 1);
        sred += __shfl_xor_sync(0xffffffffu, sred, 2);
        sred += __shfl_xor_sync(0xffffffffu, sred, 4);
        if (i == 0) out[(size_t)B * 64 + bm] = sred;
    }
}

extern "C" void kernel_launch(void* const* d_in, const int* in_sizes, int n_in,
                              void* d_out, int out_size)
{
    const float* U0  = (const float*)d_in[0];
    const float* eps = (const float*)d_in[1];
    const float* W0  = (const float*)d_in[2];
    const float* W1  = (const float*)d_in[3];
    const float* W2  = (const float*)d_in[4];

    int B = in_sizes[0] / 64;
    int smem = (HDR + MPB * MREC) * (int)sizeof(float);   // 27392 B

    cudaFuncSetAttribute(ode_kernel, cudaFuncAttributeMaxDynamicSharedMemorySize, smem);

    int blocks = (B + MPB - 1) / MPB;
    ode_kernel<<<blocks, NTH, smem>>>(U0, eps, W0, W1, W2, (float*)d_out, B);
}